// round 4
// baseline (speedup 1.0000x reference)
#include <cuda_runtime.h>
#include <cstdint>

#define USER_N 100000
#define ITEM_N 200000
#define NN     (USER_N + ITEM_N)   // 300000
#define D      64
#define E_NUM  4800000

// Scratch ping-pong buffers (static device allocation — only legal scratch).
__device__ float g_bufA[(size_t)NN * D];
__device__ float g_bufB[(size_t)NN * D];

// ---------------------------------------------------------------------------
// init: out = concat(u, i) (layer-0 acc term), bufA = same, bufB = 0
// ---------------------------------------------------------------------------
__global__ void init_kernel(const float4* __restrict__ u,
                            const float4* __restrict__ i,
                            float4* __restrict__ out,
                            float4* __restrict__ bufA,
                            float4* __restrict__ bufB) {
    const unsigned total4 = NN * D / 4;
    const unsigned usplit = USER_N * D / 4;
    unsigned idx = blockIdx.x * blockDim.x + threadIdx.x;
    if (idx >= total4) return;
    float4 v = (idx < usplit) ? u[idx] : i[idx - usplit];
    out[idx]  = v;
    bufA[idx] = v;
    bufB[idx] = make_float4(0.f, 0.f, 0.f, 0.f);
}

// ---------------------------------------------------------------------------
// Half-D COO SpMM scatter: handles a 32-float (one 128B line) slice of every
// row. x and y are pre-offset by half*32 on the host side. 8 threads/edge,
// one float4 gather + one red.global.add.v4.f32 each.
// Randomly-touched footprint per pass = 2 x 38.4MB -> L2-resident.
// ---------------------------------------------------------------------------
__global__ void __launch_bounds__(256)
spmm_half_kernel(const int* __restrict__ rows,
                 const int* __restrict__ cols,
                 const float* __restrict__ vals,
                 const float* __restrict__ x,   // + half*32
                 float* __restrict__ y) {       // + half*32
    unsigned idx = blockIdx.x * blockDim.x + threadIdx.x;
    unsigned e = idx >> 3;
    if (e >= E_NUM) return;
    unsigned part = (idx & 7u) << 2;           // 0,4,...,28

    unsigned r = (unsigned)__ldg(rows + e);
    unsigned c = (unsigned)__ldg(cols + e);
    float    v = __ldg(vals + e);

    float4 xv = *reinterpret_cast<const float4*>(x + c * (unsigned)D + part);
    float* yp = y + r * (unsigned)D + part;

    float a0 = v * xv.x, a1 = v * xv.y, a2 = v * xv.z, a3 = v * xv.w;
    asm volatile("red.global.add.v4.f32 [%0], {%1, %2, %3, %4};"
                 :: "l"(yp), "f"(a0), "f"(a1), "f"(a2), "f"(a3)
                 : "memory");
}

// ---------------------------------------------------------------------------
// out += src ; tozero = 0   (fused accumulate + next-layer zero)
// ---------------------------------------------------------------------------
__global__ void addz_kernel(const float4* __restrict__ src,
                            float4* __restrict__ out,
                            float4* __restrict__ tozero) {
    const unsigned total4 = NN * D / 4;
    unsigned idx = blockIdx.x * blockDim.x + threadIdx.x;
    if (idx >= total4) return;
    float4 s = src[idx];
    float4 o = out[idx];
    o.x += s.x; o.y += s.y; o.z += s.z; o.w += s.w;
    out[idx] = o;
    tozero[idx] = make_float4(0.f, 0.f, 0.f, 0.f);
}

// out += src (no zeroing — layer 3 scatters straight into out)
__global__ void add_kernel(const float4* __restrict__ src,
                           float4* __restrict__ out) {
    const unsigned total4 = NN * D / 4;
    unsigned idx = blockIdx.x * blockDim.x + threadIdx.x;
    if (idx >= total4) return;
    float4 s = src[idx];
    float4 o = out[idx];
    o.x += s.x; o.y += s.y; o.z += s.z; o.w += s.w;
    out[idx] = o;
}

extern "C" void kernel_launch(void* const* d_in, const int* in_sizes, int n_in,
                              void* d_out, int out_size) {
    const int*   rows = (const int*)  d_in[0];
    const int*   cols = (const int*)  d_in[1];
    const float* vals = (const float*)d_in[2];
    const float* uEmb = (const float*)d_in[3];
    const float* iEmb = (const float*)d_in[4];
    float* out = (float*)d_out;

    float* bufA; cudaGetSymbolAddress((void**)&bufA, g_bufA);
    float* bufB; cudaGetSymbolAddress((void**)&bufB, g_bufB);

    const int THREADS = 256;
    const unsigned total4 = NN * D / 4;
    const int gridDense = (int)((total4 + THREADS - 1) / THREADS);
    const int gridSpmm  = (int)(((size_t)E_NUM * 8 + THREADS - 1) / THREADS);

    // out = acc0 = X0 ; bufA = X0 ; bufB = 0
    init_kernel<<<gridDense, THREADS>>>((const float4*)uEmb, (const float4*)iEmb,
                                        (float4*)out, (float4*)bufA, (float4*)bufB);

    // layer 1: B = Adj*A (two L2-resident half passes); out += B ; A = 0
    spmm_half_kernel<<<gridSpmm, THREADS>>>(rows, cols, vals, bufA,      bufB);
    spmm_half_kernel<<<gridSpmm, THREADS>>>(rows, cols, vals, bufA + 32, bufB + 32);
    addz_kernel<<<gridDense, THREADS>>>((const float4*)bufB, (float4*)out, (float4*)bufA);

    // layer 2: A = Adj*B ; out += A
    spmm_half_kernel<<<gridSpmm, THREADS>>>(rows, cols, vals, bufB,      bufA);
    spmm_half_kernel<<<gridSpmm, THREADS>>>(rows, cols, vals, bufB + 32, bufA + 32);
    add_kernel<<<gridDense, THREADS>>>((const float4*)bufA, (float4*)out);

    // layer 3: out += Adj*A   (scatter directly into the accumulator)
    spmm_half_kernel<<<gridSpmm, THREADS>>>(rows, cols, vals, bufA,      out);
    spmm_half_kernel<<<gridSpmm, THREADS>>>(rows, cols, vals, bufA + 32, out + 32);
}

// round 5
// speedup vs baseline: 1.4970x; 1.4970x over previous
#include <cuda_runtime.h>
#include <cstdint>

#define USER_N 100000
#define ITEM_N 200000
#define NN     (USER_N + ITEM_N)   // 300000
#define D      64
#define E_NUM  4800000

#define SCAN_BS 512
#define SCAN_NB ((NN + SCAN_BS - 1) / SCAN_BS)   // 586

// ---- static device scratch (only legal scratch under harness guards) ----
__device__ float g_bufA[(size_t)NN * D];
__device__ float g_bufB[(size_t)NN * D];
__device__ int2  g_cv[E_NUM];          // packed (col, val-bits) in CSR order
__device__ int   g_counts[NN];         // per-row edge counts (lengths)
__device__ int   g_offsets[NN];        // exclusive prefix of counts
__device__ int   g_cursor[NN];         // scatter cursors (copy of offsets)
__device__ int   g_blockSums[SCAN_NB];

// ---------------------------------------------------------------------------
// init: out = concat(u,i) (layer-0 acc term); counts = 0
// ---------------------------------------------------------------------------
__global__ void init_kernel(const float4* __restrict__ u,
                            const float4* __restrict__ i,
                            float4* __restrict__ out,
                            int* __restrict__ counts) {
    const unsigned total4 = NN * D / 4;
    const unsigned usplit = USER_N * D / 4;
    unsigned idx = blockIdx.x * blockDim.x + threadIdx.x;
    if (idx < (unsigned)NN) counts[idx] = 0;
    if (idx >= total4) return;
    out[idx] = (idx < usplit) ? u[idx] : i[idx - usplit];
}

// histogram of destination rows (RED, no return value used)
__global__ void hist_kernel(const int* __restrict__ rows, int* __restrict__ counts) {
    unsigned e = blockIdx.x * blockDim.x + threadIdx.x;
    if (e >= E_NUM) return;
    atomicAdd(counts + __ldg(rows + e), 1);
}

// ---- 3-kernel exclusive scan of counts -> offsets (and blockSums) ----
__global__ void scan1_kernel(const int* __restrict__ counts,
                             int* __restrict__ offsets,
                             int* __restrict__ blockSums) {
    __shared__ int sh[SCAN_BS];
    int t = threadIdx.x;
    int i = blockIdx.x * SCAN_BS + t;
    int v = (i < NN) ? counts[i] : 0;
    sh[t] = v;
    __syncthreads();
    for (int ofs = 1; ofs < SCAN_BS; ofs <<= 1) {
        int add = (t >= ofs) ? sh[t - ofs] : 0;
        __syncthreads();
        sh[t] += add;
        __syncthreads();
    }
    if (i < NN) offsets[i] = sh[t] - v;               // exclusive
    if (t == SCAN_BS - 1) blockSums[blockIdx.x] = sh[t];
}

__global__ void scan2_kernel(int* __restrict__ blockSums) {
    __shared__ int sh[1024];
    int t = threadIdx.x;
    int v = (t < SCAN_NB) ? blockSums[t] : 0;
    sh[t] = v;
    __syncthreads();
    for (int ofs = 1; ofs < 1024; ofs <<= 1) {
        int add = (t >= ofs) ? sh[t - ofs] : 0;
        __syncthreads();
        sh[t] += add;
        __syncthreads();
    }
    if (t < SCAN_NB) blockSums[t] = sh[t] - v;        // exclusive
}

__global__ void scan3_kernel(int* __restrict__ offsets,
                             const int* __restrict__ blockSums,
                             int* __restrict__ cursor) {
    int i = blockIdx.x * SCAN_BS + threadIdx.x;
    if (i >= NN) return;
    int o = offsets[i] + blockSums[blockIdx.x * SCAN_BS / SCAN_BS == 0 ? 0 : 0];
    // (grid is sized so blockIdx.x indexes the same SCAN_BS blocks as scan1)
    o = offsets[i] + blockSums[blockIdx.x];
    offsets[i] = o;
    cursor[i]  = o;
}

// scatter edges into CSR order: cv[pos] = (col, val)
__global__ void scatter_kernel(const int* __restrict__ rows,
                               const int* __restrict__ cols,
                               const float* __restrict__ vals,
                               int* __restrict__ cursor,
                               int2* __restrict__ cv) {
    unsigned e = blockIdx.x * blockDim.x + threadIdx.x;
    if (e >= E_NUM) return;
    int r = __ldg(rows + e);
    int pos = atomicAdd(cursor + r, 1);
    cv[pos] = make_int2(__ldg(cols + e), __float_as_int(__ldg(vals + e)));
}

// ---------------------------------------------------------------------------
// CSR SpMM, warp per row, fused accumulator update.
//   y[row]   = sum_e val*x[col]        (if WRITE_Y)
//   acc[row] += sum
// Each lane owns 2 consecutive floats of D (32 lanes * 2 = 64).
// SPLIT_X: gather from uEmb/iEmb pair instead of a contiguous x (layer 1).
// ---------------------------------------------------------------------------
template <bool WRITE_Y, bool SPLIT_X>
__global__ void __launch_bounds__(256)
csr_spmm_kernel(const int* __restrict__ off,
                const int* __restrict__ cnt,
                const int2* __restrict__ cv,
                const float* __restrict__ x,      // contiguous [NN,64] (if !SPLIT_X)
                const float* __restrict__ xu,     // uEmb (if SPLIT_X)
                const float* __restrict__ xi,     // iEmb (if SPLIT_X)
                float* __restrict__ y,
                float* __restrict__ acc) {
    unsigned warpId = (blockIdx.x * blockDim.x + threadIdx.x) >> 5;
    if (warpId >= (unsigned)NN) return;
    unsigned lane = threadIdx.x & 31u;
    unsigned row = warpId;

    int start = __ldg(off + row);
    int n     = __ldg(cnt + row);

    float sx = 0.f, sy = 0.f;
    for (int base = 0; base < n; base += 32) {
        int k = base + (int)lane;
        int2 pr = make_int2(0, 0);
        if (k < n) pr = __ldg(cv + start + k);
        int m = min(32, n - base);
        #pragma unroll 4
        for (int j = 0; j < m; j++) {
            int   c = __shfl_sync(0xffffffffu, pr.x, j);
            float v = __int_as_float(__shfl_sync(0xffffffffu, pr.y, j));
            const float* xr;
            if (SPLIT_X) {
                xr = (c < USER_N) ? (xu + (size_t)c * D)
                                  : (xi + (size_t)(c - USER_N) * D);
            } else {
                xr = x + (size_t)c * D;
            }
            float2 xv = __ldg(reinterpret_cast<const float2*>(xr) + lane);
            sx += v * xv.x;
            sy += v * xv.y;
        }
    }

    size_t o = (size_t)row * D + lane * 2;
    if (WRITE_Y) {
        *reinterpret_cast<float2*>(y + o) = make_float2(sx, sy);
    }
    float2 a = *reinterpret_cast<float2*>(acc + o);
    a.x += sx; a.y += sy;
    *reinterpret_cast<float2*>(acc + o) = a;
}

extern "C" void kernel_launch(void* const* d_in, const int* in_sizes, int n_in,
                              void* d_out, int out_size) {
    const int*   rows = (const int*)  d_in[0];
    const int*   cols = (const int*)  d_in[1];
    const float* vals = (const float*)d_in[2];
    const float* uEmb = (const float*)d_in[3];
    const float* iEmb = (const float*)d_in[4];
    float* out = (float*)d_out;

    float* bufA;   cudaGetSymbolAddress((void**)&bufA,   g_bufA);
    float* bufB;   cudaGetSymbolAddress((void**)&bufB,   g_bufB);
    int2*  cv;     cudaGetSymbolAddress((void**)&cv,     g_cv);
    int*   counts; cudaGetSymbolAddress((void**)&counts, g_counts);
    int*   offs;   cudaGetSymbolAddress((void**)&offs,   g_offsets);
    int*   cursor; cudaGetSymbolAddress((void**)&cursor, g_cursor);
    int*   bsums;  cudaGetSymbolAddress((void**)&bsums,  g_blockSums);

    const int T = 256;
    const int gridDense = (NN * D / 4 + T - 1) / T;       // covers NN for counts-zero too
    const int gridE     = (E_NUM + T - 1) / T;
    const int gridSpmm  = (NN * 32 + T - 1) / T;          // warp per row

    // ---- build phase ----
    init_kernel<<<gridDense, T>>>((const float4*)uEmb, (const float4*)iEmb,
                                  (float4*)out, counts);
    hist_kernel<<<gridE, T>>>(rows, counts);
    scan1_kernel<<<SCAN_NB, SCAN_BS>>>(counts, offs, bsums);
    scan2_kernel<<<1, 1024>>>(bsums);
    scan3_kernel<<<SCAN_NB, SCAN_BS>>>(offs, bsums, cursor);
    scatter_kernel<<<gridE, T>>>(rows, cols, vals, cursor, cv);

    // ---- 3 propagation layers, acc fused into epilogue ----
    // layer 1: Y1 = Adj * X0 (gather straight from uEmb/iEmb); out += Y1
    csr_spmm_kernel<true,  true ><<<gridSpmm, T>>>(offs, counts, cv,
                                                   nullptr, uEmb, iEmb, bufB, out);
    // layer 2: Y2 = Adj * Y1; out += Y2
    csr_spmm_kernel<true,  false><<<gridSpmm, T>>>(offs, counts, cv,
                                                   bufB, nullptr, nullptr, bufA, out);
    // layer 3: out += Adj * Y2 (y not needed)
    csr_spmm_kernel<false, false><<<gridSpmm, T>>>(offs, counts, cv,
                                                   bufA, nullptr, nullptr, bufB, out);
}

// round 6
// speedup vs baseline: 1.5850x; 1.0588x over previous
#include <cuda_runtime.h>
#include <cstdint>

#define USER_N 100000
#define ITEM_N 200000
#define NN     (USER_N + ITEM_N)   // 300000
#define D      64
#define E_NUM  4800000

#define SCAN_BS 512
#define SCAN_NB ((NN + SCAN_BS - 1) / SCAN_BS)   // 586

// ---- static device scratch (only legal scratch under harness guards) ----
__device__ float g_bufA[(size_t)NN * D];
__device__ float g_bufB[(size_t)NN * D];
__device__ int2  g_cv[E_NUM];          // packed (col, val-bits) in CSR order
__device__ int   g_counts[NN];
__device__ int   g_offsets[NN];
__device__ int   g_cursor[NN];
__device__ int   g_blockSums[SCAN_NB];

// ---------------------------------------------------------------------------
// init: out = concat(u,i) (layer-0 acc term); counts = 0
// ---------------------------------------------------------------------------
__global__ void init_kernel(const float4* __restrict__ u,
                            const float4* __restrict__ i,
                            float4* __restrict__ out,
                            int* __restrict__ counts) {
    const unsigned total4 = NN * D / 4;
    const unsigned usplit = USER_N * D / 4;
    unsigned idx = blockIdx.x * blockDim.x + threadIdx.x;
    if (idx < (unsigned)NN) counts[idx] = 0;
    if (idx >= total4) return;
    out[idx] = (idx < usplit) ? u[idx] : i[idx - usplit];
}

__global__ void hist_kernel(const int* __restrict__ rows, int* __restrict__ counts) {
    unsigned e = blockIdx.x * blockDim.x + threadIdx.x;
    if (e >= E_NUM) return;
    atomicAdd(counts + __ldg(rows + e), 1);
}

// ---- 3-kernel exclusive scan of counts -> offsets ----
__global__ void scan1_kernel(const int* __restrict__ counts,
                             int* __restrict__ offsets,
                             int* __restrict__ blockSums) {
    __shared__ int sh[SCAN_BS];
    int t = threadIdx.x;
    int i = blockIdx.x * SCAN_BS + t;
    int v = (i < NN) ? counts[i] : 0;
    sh[t] = v;
    __syncthreads();
    for (int ofs = 1; ofs < SCAN_BS; ofs <<= 1) {
        int add = (t >= ofs) ? sh[t - ofs] : 0;
        __syncthreads();
        sh[t] += add;
        __syncthreads();
    }
    if (i < NN) offsets[i] = sh[t] - v;
    if (t == SCAN_BS - 1) blockSums[blockIdx.x] = sh[t];
}

__global__ void scan2_kernel(int* __restrict__ blockSums) {
    __shared__ int sh[1024];
    int t = threadIdx.x;
    int v = (t < SCAN_NB) ? blockSums[t] : 0;
    sh[t] = v;
    __syncthreads();
    for (int ofs = 1; ofs < 1024; ofs <<= 1) {
        int add = (t >= ofs) ? sh[t - ofs] : 0;
        __syncthreads();
        sh[t] += add;
        __syncthreads();
    }
    if (t < SCAN_NB) blockSums[t] = sh[t] - v;
}

__global__ void scan3_kernel(int* __restrict__ offsets,
                             const int* __restrict__ blockSums,
                             int* __restrict__ cursor) {
    int i = blockIdx.x * SCAN_BS + threadIdx.x;
    if (i >= NN) return;
    int o = offsets[i] + blockSums[blockIdx.x];
    offsets[i] = o;
    cursor[i]  = o;
}

__global__ void scatter_kernel(const int* __restrict__ rows,
                               const int* __restrict__ cols,
                               const float* __restrict__ vals,
                               int* __restrict__ cursor,
                               int2* __restrict__ cv) {
    unsigned e = blockIdx.x * blockDim.x + threadIdx.x;
    if (e >= E_NUM) return;
    int r = __ldg(rows + e);
    int pos = atomicAdd(cursor + r, 1);
    cv[pos] = make_int2(__ldg(cols + e), __float_as_int(__ldg(vals + e)));
}

// ---------------------------------------------------------------------------
// CSR SpMM v2: warp per row, 2 edges per iteration.
//   lanes 0-15  handle edge j   (each lane gathers one float4 of x[col_j])
//   lanes 16-31 handle edge j+1
// Accumulators merged at the end via shfl_xor(16).
// cv is streamed with __ldcs; acc RMW uses __ldcs/__stcs so the x gather
// table keeps L2.
// ---------------------------------------------------------------------------
template <bool WRITE_Y, bool SPLIT_X>
__global__ void __launch_bounds__(256)
csr_spmm_kernel(const int* __restrict__ off,
                const int* __restrict__ cnt,
                const int2* __restrict__ cv,
                const float4* __restrict__ x,     // [NN,16] float4 (if !SPLIT_X)
                const float4* __restrict__ xu,    // uEmb (if SPLIT_X)
                const float4* __restrict__ xi,    // iEmb (if SPLIT_X)
                float4* __restrict__ y,
                float4* __restrict__ acc) {
    unsigned warpId = (blockIdx.x * blockDim.x + threadIdx.x) >> 5;
    if (warpId >= (unsigned)NN) return;
    const unsigned lane = threadIdx.x & 31u;
    const unsigned half = lane >> 4;        // which edge of the pair
    const unsigned q    = lane & 15u;       // float4 slot within the row
    const unsigned row  = warpId;

    int start = __ldg(off + row);
    int n     = __ldg(cnt + row);

    float4 s = make_float4(0.f, 0.f, 0.f, 0.f);

    for (int base = 0; base < n; base += 32) {
        int k = base + (int)lane;
        int2 pr = make_int2(0, 0);
        if (k < n) pr = __ldcs(cv + start + k);
        int m = min(32, n - base);
        #pragma unroll 8
        for (int j = 0; j < m; j += 2) {
            int jj = j + (int)half;         // zero-padded pr covers jj == m
            int   c = __shfl_sync(0xffffffffu, pr.x, jj);
            float v = __int_as_float(__shfl_sync(0xffffffffu, pr.y, jj));
            const float4* xr;
            if (SPLIT_X) {
                xr = (c < USER_N) ? (xu + (size_t)c * (D / 4))
                                  : (xi + (size_t)(c - USER_N) * (D / 4));
            } else {
                xr = x + (size_t)c * (D / 4);
            }
            float4 xv = __ldg(xr + q);
            s.x += v * xv.x;
            s.y += v * xv.y;
            s.z += v * xv.z;
            s.w += v * xv.w;
        }
    }

    // merge the two half-warp accumulators
    s.x += __shfl_xor_sync(0xffffffffu, s.x, 16);
    s.y += __shfl_xor_sync(0xffffffffu, s.y, 16);
    s.z += __shfl_xor_sync(0xffffffffu, s.z, 16);
    s.w += __shfl_xor_sync(0xffffffffu, s.w, 16);

    if (lane < 16) {
        size_t o = (size_t)row * (D / 4) + q;
        if (WRITE_Y) y[o] = s;              // next layer's gather table: keep cached
        float4 a = __ldcs(acc + o);
        a.x += s.x; a.y += s.y; a.z += s.z; a.w += s.w;
        __stcs(acc + o, a);
    }
}

extern "C" void kernel_launch(void* const* d_in, const int* in_sizes, int n_in,
                              void* d_out, int out_size) {
    const int*   rows = (const int*)  d_in[0];
    const int*   cols = (const int*)  d_in[1];
    const float* vals = (const float*)d_in[2];
    const float* uEmb = (const float*)d_in[3];
    const float* iEmb = (const float*)d_in[4];
    float* out = (float*)d_out;

    float* bufA;   cudaGetSymbolAddress((void**)&bufA,   g_bufA);
    float* bufB;   cudaGetSymbolAddress((void**)&bufB,   g_bufB);
    int2*  cv;     cudaGetSymbolAddress((void**)&cv,     g_cv);
    int*   counts; cudaGetSymbolAddress((void**)&counts, g_counts);
    int*   offs;   cudaGetSymbolAddress((void**)&offs,   g_offsets);
    int*   cursor; cudaGetSymbolAddress((void**)&cursor, g_cursor);
    int*   bsums;  cudaGetSymbolAddress((void**)&bsums,  g_blockSums);

    const int T = 256;
    const int gridDense = (NN * D / 4 + T - 1) / T;
    const int gridE     = (E_NUM + T - 1) / T;
    const int gridSpmm  = (NN * 32 + T - 1) / T;          // warp per row

    // ---- build phase ----
    init_kernel<<<gridDense, T>>>((const float4*)uEmb, (const float4*)iEmb,
                                  (float4*)out, counts);
    hist_kernel<<<gridE, T>>>(rows, counts);
    scan1_kernel<<<SCAN_NB, SCAN_BS>>>(counts, offs, bsums);
    scan2_kernel<<<1, 1024>>>(bsums);
    scan3_kernel<<<SCAN_NB, SCAN_BS>>>(offs, bsums, cursor);
    scatter_kernel<<<gridE, T>>>(rows, cols, vals, cursor, cv);

    // ---- 3 propagation layers, acc fused into epilogue ----
    csr_spmm_kernel<true,  true ><<<gridSpmm, T>>>(offs, counts, cv,
        nullptr, (const float4*)uEmb, (const float4*)iEmb,
        (float4*)bufB, (float4*)out);
    csr_spmm_kernel<true,  false><<<gridSpmm, T>>>(offs, counts, cv,
        (const float4*)bufB, nullptr, nullptr,
        (float4*)bufA, (float4*)out);
    csr_spmm_kernel<false, false><<<gridSpmm, T>>>(offs, counts, cv,
        (const float4*)bufA, nullptr, nullptr,
        (float4*)bufB, (float4*)out);
}